// round 5
// baseline (speedup 1.0000x reference)
#include <cuda_runtime.h>
#include <math.h>
#include <float.h>

// WaveNet autoregressive generation, sm_103a — round 4: 512 threads/CTA.
// 64 CTAs x 2 rows (L2-traffic-optimal R=2), 16 warps = 4 per scheduler for
// latency hiding (round-3 bottleneck: 2 warps/SMSP, issue=29%).
// Weight loads software-pipelined into register buffers one phase ahead.
// Partial-sum smem is unioned (conv partials dead before res/skip written)
// to stay under the 48KB static smem limit.

#define NLAYER 30
#define CCH 64
#define SCH 256
#define VV  256
#define BB  128
#define RING_PER_ROW 3069   // 3 * (2^10 - 1) slots, 64 floats each

__device__ float g_ring[(size_t)BB * RING_PER_ROW * CCH];  // ~100.6 MB scratch

template<int N>
__device__ __forceinline__ void wload(float4* dst, const float* __restrict__ W,
                                      int wstride4, int kb, int jq) {
    const float4* W4 = (const float4*)W;
#pragma unroll
    for (int u = 0; u < N; u++)
        dst[u] = W4[(size_t)(kb + u) * wstride4 + jq];
}

template<int N>
__device__ __forceinline__ void mmacc(const float* __restrict__ a0,
                                      const float* __restrict__ a1,
                                      const float4* w, int kb,
                                      float4& o0, float4& o1) {
#pragma unroll
    for (int u = 0; u < N; u++) {
        float x0 = a0[kb + u], x1 = a1[kb + u];
        o0.x = fmaf(x0, w[u].x, o0.x);
        o0.y = fmaf(x0, w[u].y, o0.y);
        o0.z = fmaf(x0, w[u].z, o0.z);
        o0.w = fmaf(x0, w[u].w, o0.w);
        o1.x = fmaf(x1, w[u].x, o1.x);
        o1.y = fmaf(x1, w[u].y, o1.y);
        o1.z = fmaf(x1, w[u].z, o1.z);
        o1.w = fmaf(x1, w[u].w, o1.w);
    }
}

template<int N>
__device__ __forceinline__ void mmld(const float* __restrict__ a0,
                                     const float* __restrict__ a1,
                                     const float* __restrict__ W,
                                     int wstride4, int kb, int jq,
                                     float4& o0, float4& o1) {
    const float4* W4 = (const float4*)W;
#pragma unroll
    for (int u = 0; u < N; u++) {
        float4 w = W4[(size_t)(kb + u) * wstride4 + jq];
        float x0 = a0[kb + u], x1 = a1[kb + u];
        o0.x = fmaf(x0, w.x, o0.x);
        o0.y = fmaf(x0, w.y, o0.y);
        o0.z = fmaf(x0, w.z, o0.z);
        o0.w = fmaf(x0, w.w, o0.w);
        o1.x = fmaf(x1, w.x, o1.x);
        o1.y = fmaf(x1, w.y, o1.y);
        o1.z = fmaf(x1, w.z, o1.z);
        o1.w = fmaf(x1, w.w, o1.w);
    }
}

__global__ __launch_bounds__(512, 1)
void wavenet_kernel(const int* __restrict__ seed,
                    const float* __restrict__ emb,     // (V, C)
                    const float* __restrict__ kern,    // (L, 2, C, 2C)
                    const float* __restrict__ cbias,   // (L, 2C)
                    const float* __restrict__ rw,      // (L, C, C)
                    const float* __restrict__ rb,      // (L, C)
                    const float* __restrict__ sw,      // (L, C, S)
                    const float* __restrict__ sb,      // (L, S)
                    const float* __restrict__ ow0,     // (S, V)
                    const float* __restrict__ ob0,     // (V)
                    const float* __restrict__ ow1,     // (V, V)
                    const float* __restrict__ ob1,     // (V)
                    float* __restrict__ out,
                    int T, long long samp_off, long long logit_off, int mode)
{
    __shared__ __align__(16) float sx[2][CCH];
    __shared__ __align__(16) float sxl[2][CCH];
    __shared__ __align__(16) float sg[2][CCH];
    __shared__ __align__(16) float sskip[2][SCH];
    __shared__ __align__(16) float sh0[2][SCH];
    __shared__ __align__(16) float slg[2][VV];
    // 32KB union: scp (conv partials) overlaps srp+ssp (res/skip partials).
    // scp is consumed in the gate phase, before srp/ssp are written.
    __shared__ __align__(16) float sbuf[8192];
    __shared__ int snidx[2];

    float (*scp)[2][128] = (float(*)[2][128])sbuf;            // [16][2][128]
    float (*srp)[2][64]  = (float(*)[2][64])sbuf;             // [32][2][64]
    float (*ssp)[2][256] = (float(*)[2][256])(sbuf + 4096);   // [8][2][256]

    const int tid = threadIdx.x;
    const int row0 = blockIdx.x * 2;

    // phase-specific thread mappings (512 threads)
    const int jqc = tid & 31, ksc = tid >> 5, kbc = ksc * 4;   // conv: 32jq x 16ks(4)
    const int jqr = tid & 15, ksr = tid >> 4, kbr = ksr * 2;   // res : 16jq x 32ks(2)
    const int jqs = tid & 63, kss = tid >> 6, kbs = kss * 8;   // skip: 64jq x 8ks(8)
    const int jqh = tid & 63, ksh = tid >> 6, kbh = ksh * 32;  // head: 64jq x 8ks(32)
    const int r = tid >> 6, c = tid & 63;                      // tid<128 combines
    const int r2 = tid >> 8, c2 = tid & 255;                   // 512-wide combines

    float4 wk[8];   // conv K0(4)|K1(4) prefetch, or head chunk [kbh, kbh+8)
    float4 wr[2];   // res prefetch
    float4 ws[8];   // skip prefetch, or head chunk [kbh+8, kbh+16)
    float  rpop = 0.f;

    if (tid < 2) snidx[tid] = seed[row0 + tid];

    // prefetch conv weights for (t=0, layer 0); rpop(layer0,t=0)=0 (t<d)
    wload<4>(wk,     kern,             32, kbc, jqc);
    wload<4>(wk + 4, kern + CCH * 128, 32, kbc, jqc);
    __syncthreads();

#pragma unroll 1
    for (int t = 0; t < T; t++) {
        // ---- step head: embedding lookup, seed sxl for layer 0, zero skip ----
        if (tid < 128) {
            sx[r][c] = emb[(size_t)snidx[r] * CCH + c];
            sxl[r][c] = rpop;
        }
        sskip[r2][c2] = 0.f;
        __syncthreads();

#pragma unroll 1
        for (int i = 0; i < NLAYER; i++) {
            const int d = 1 << (i % 10);
            const long long off = (long long)(i / 10) * 1023 + (d - 1);

            // ---- Phase A: conv FMA (prefetched wk) + ring push + wr/ws prefetch
            {
                float4 o0 = {0, 0, 0, 0}, o1 = {0, 0, 0, 0};
                mmacc<4>(sxl[0], sxl[1], wk,     kbc, o0, o1);
                mmacc<4>(sx[0],  sx[1],  wk + 4, kbc, o0, o1);
                *(float4*)&scp[ksc][0][4 * jqc] = o0;
                *(float4*)&scp[ksc][1][4 * jqc] = o1;
            }
            if (tid < 128) {
                size_t idx = ((size_t)(row0 + r) * RING_PER_ROW + (size_t)off
                              + (t & (d - 1))) * CCH + c;
                g_ring[idx] = sx[r][c];                 // push x_i (pop already done)
            }
            wload<2>(wr, rw + (size_t)i * CCH * CCH, 16, kbr, jqr);
            wload<8>(ws, sw + (size_t)i * CCH * SCH, 64, kbs, jqs);
            __syncthreads();

            // ---- Phase B: gate + prefetch next conv weights & next queue pop ----
            if (i < NLAYER - 1) {
                const float* kn = kern + (size_t)(i + 1) * 2 * CCH * 128;
                wload<4>(wk,     kn,             32, kbc, jqc);
                wload<4>(wk + 4, kn + CCH * 128, 32, kbc, jqc);
                if (tid < 128) {
                    const int d2 = 1 << ((i + 1) % 10);
                    const long long off2 = (long long)((i + 1) / 10) * 1023 + (d2 - 1);
                    size_t idx2 = ((size_t)(row0 + r) * RING_PER_ROW + (size_t)off2
                                   + (t & (d2 - 1))) * CCH + c;
                    rpop = (t >= d2) ? g_ring[idx2] : 0.f;
                }
            } else {
                wload<8>(wk, ow0, 64, kbh, jqh);        // head W0 rows [kbh, kbh+8)
            }
            if (tid < 128) {
                float ht = cbias[i * 128 + c];
                float hs = cbias[i * 128 + 64 + c];
#pragma unroll
                for (int ks = 0; ks < 16; ks++) {
                    ht += scp[ks][r][c];
                    hs += scp[ks][r][c + 64];
                }
                sg[r][c] = tanhf(ht) * (1.f / (1.f + expf(-hs)));
            }
            __syncthreads();

            // ---- Phase C: res + skip FMA (prefetched wr/ws) ----
            {
                float4 o0 = {0, 0, 0, 0}, o1 = {0, 0, 0, 0};
                mmacc<2>(sg[0], sg[1], wr, kbr, o0, o1);
                *(float4*)&srp[ksr][0][4 * jqr] = o0;
                *(float4*)&srp[ksr][1][4 * jqr] = o1;
            }
            {
                float4 o0 = {0, 0, 0, 0}, o1 = {0, 0, 0, 0};
                mmacc<8>(sg[0], sg[1], ws, kbs, o0, o1);
                *(float4*)&ssp[kss][0][4 * jqs] = o0;
                *(float4*)&ssp[kss][1][4 * jqs] = o1;
            }
            __syncthreads();

            // ---- Phase D: combine (x update, skip accum, stage next sxl) ----
            if (tid < 128) {
                float v = sx[r][c] + rb[i * 64 + c];
#pragma unroll
                for (int ks = 0; ks < 32; ks++) v += srp[ks][r][c];
                sx[r][c] = v;
                if (i < NLAYER - 1) sxl[r][c] = rpop;
            }
            {
                float s = sskip[r2][c2] + sb[i * 256 + c2];
#pragma unroll
                for (int ks = 0; ks < 8; ks++) s += ssp[ks][r2][c2];
                if (i == NLAYER - 1) s = fmaxf(s, 0.f);
                sskip[r2][c2] = s;
            }
            if (i == NLAYER - 1)
                wload<8>(ws, ow0, 64, kbh + 8, jqh);    // head W0 rows [kbh+8,+16)
            __syncthreads();
        }

        // ---- head H1: h0_partial = relu(skip) @ out_w0 (16 prefetched + 16 inline)
        {
            float4 o0 = {0, 0, 0, 0}, o1 = {0, 0, 0, 0};
            mmacc<8>(sskip[0], sskip[1], wk, kbh,     o0, o1);
            mmacc<8>(sskip[0], sskip[1], ws, kbh + 8, o0, o1);
            mmld<16>(sskip[0], sskip[1], ow0, 64, kbh + 16, jqh, o0, o1);
            *(float4*)&ssp[ksh][0][4 * jqh] = o0;
            *(float4*)&ssp[ksh][1][4 * jqh] = o1;
        }
        __syncthreads();

        // ---- head H2: h0 combine + relu; prefetch half of out_w1 ----
        wload<8>(wk, ow1, 64, kbh,     jqh);
        wload<8>(ws, ow1, 64, kbh + 8, jqh);
        {
            float v = ob0[c2];
#pragma unroll
            for (int ks = 0; ks < 8; ks++) v += ssp[ks][r2][c2];
            sh0[r2][c2] = fmaxf(v, 0.f);
        }
        __syncthreads();

        // ---- head H3: logits_partial = h0 @ out_w1 ----
        {
            float4 o0 = {0, 0, 0, 0}, o1 = {0, 0, 0, 0};
            mmacc<8>(sh0[0], sh0[1], wk, kbh,     o0, o1);
            mmacc<8>(sh0[0], sh0[1], ws, kbh + 8, o0, o1);
            mmld<16>(sh0[0], sh0[1], ow1, 64, kbh + 16, jqh, o0, o1);
            *(float4*)&ssp[ksh][0][4 * jqh] = o0;
            *(float4*)&ssp[ksh][1][4 * jqh] = o1;
        }
        __syncthreads();

        // ---- head H4: logits combine + store; prefetch (t+1, layer0) conv & pop
        wload<4>(wk,     kern,             32, kbc, jqc);
        wload<4>(wk + 4, kern + CCH * 128, 32, kbc, jqc);
        if (tid < 128) {   // layer 0 pop for t+1: slot is always base (d=1)
            size_t idx0 = ((size_t)(row0 + r) * RING_PER_ROW) * CCH + c;
            rpop = g_ring[idx0];
        }
        {
            float v = ob1[c2];
#pragma unroll
            for (int ks = 0; ks < 8; ks++) v += ssp[ks][r2][c2];
            slg[r2][c2] = v;
            if (mode & 2)
                out[logit_off + ((size_t)(row0 + r2) * T + t) * VV + c2] = v;
        }
        __syncthreads();

        // ---- head H5: argmax per row (first-max tie rule, matches jnp.argmax) ----
        if (tid < 64) {
            int rr = tid >> 5, lane = tid & 31;
            float bv = -FLT_MAX;
            int bi = 0;
#pragma unroll
            for (int jj = 0; jj < 8; jj++) {
                int j = lane + jj * 32;
                float v = slg[rr][j];
                if (v > bv) { bv = v; bi = j; }
            }
#pragma unroll
            for (int o = 16; o > 0; o >>= 1) {
                float ov = __shfl_down_sync(0xffffffffu, bv, o);
                int   oi = __shfl_down_sync(0xffffffffu, bi, o);
                if (ov > bv || (ov == bv && oi < bi)) { bv = ov; bi = oi; }
            }
            if (lane == 0) {
                snidx[rr] = bi;
                if (mode & 1) out[samp_off + (size_t)(row0 + rr) * T + t] = (float)bi;
                if (mode & 4) ((int*)out)[(size_t)(row0 + rr) * T + t] = bi;
            }
        }
        __syncthreads();
    }
}

extern "C" void kernel_launch(void* const* d_in, const int* in_sizes, int n_in,
                              void* d_out, int out_size) {
    const int*   seed  = (const int*)d_in[0];
    const float* emb   = (const float*)d_in[1];
    const float* kern  = (const float*)d_in[2];
    const float* cbias = (const float*)d_in[3];
    const float* rw    = (const float*)d_in[4];
    const float* rb    = (const float*)d_in[5];
    const float* sw    = (const float*)d_in[6];
    const float* sb    = (const float*)d_in[7];
    const float* ow0   = (const float*)d_in[8];
    const float* ob0   = (const float*)d_in[9];
    const float* ow1   = (const float*)d_in[10];
    const float* ob1   = (const float*)d_in[11];
    (void)in_sizes; (void)n_in;

    int T, mode;
    long long samp_off = 0, logit_off = 0;
    if (out_size % (BB * (VV + 1)) == 0) {
        T = out_size / (BB * (VV + 1));
        mode = 1 | 2;                       // float samples then logits
        samp_off = 0;
        logit_off = (long long)BB * T;
    } else if (out_size % (BB * VV) == 0) {
        T = out_size / (BB * VV);
        mode = 2;                           // logits only
        logit_off = 0;
    } else {
        T = out_size / BB;
        mode = 4;                           // int32 samples only
    }

    wavenet_kernel<<<BB / 2, 512>>>(seed, emb, kern, cbias, rw, rb, sw, sb,
                                    ow0, ob0, ow1, ob1,
                                    (float*)d_out, T, samp_off, logit_off, mode);
}